// round 5
// baseline (speedup 1.0000x reference)
#include <cuda_runtime.h>
#include <math.h>

#define BB    128
#define TT    1024
#define IND   256
#define HH    512
#define NH    1024          // 2*H
#define FC1N  2048
#define OUTN  128
#define EPSF  1e-5f

#define M_BIG (TT * BB)
#define NCTA  128           // persistent recurrence grid
#define GNUM  32            // CTAs per independent sync group (bt x direction)
#define SROW  129           // smem row stride in float4 (odd -> bank-group step 1)
#define RNN_SMEM ((16 + 64) * SROW * 16)   // 165,120 bytes

typedef unsigned long long ull;

// packed dual-fp32 fma (f32x2). Each 32-bit lane should be an exact fp32 fma.
__device__ __forceinline__ ull fma2(ull a, ull b, ull c) {
    ull d;
    asm("fma.rn.f32x2 %0, %1, %2, %3;" : "=l"(d) : "l"(a), "l"(b), "l"(c));
    return d;
}
__device__ __forceinline__ float lo32(ull v) { return __uint_as_float((unsigned)v); }
__device__ __forceinline__ float hi32(ull v) { return __uint_as_float((unsigned)(v >> 32)); }
__device__ __forceinline__ ull pack2(float lo, float hi) {
    return (ull)__float_as_uint(lo) | ((ull)__float_as_uint(hi) << 32);
}

// ---------------- device scratch ----------------
__device__ float g_P[TT * BB * NH];      // 512 MB: P0 then P1
__device__ float g_H0buf[TT * BB * NH];  // 512 MB: all layer-0 hidden states
__device__ float g_hi0[BB * NH];
__device__ float g_hi1[BB * NH];
__device__ float g_h1a[BB * NH];
__device__ float g_h1b[BB * NH];
__device__ float g_bias0[NH];
__device__ float g_bias1[NH];
__device__ float g_y1[BB * NH];
__device__ float g_z[BB * FC1N];
__device__ int   g_ctr0[TT * 4];         // per-step, per-group barrier counters
__device__ int   g_ctr1[TT * 4];
__device__ int   g_use2;                 // runtime canary: is fma.rn.f32x2 sane?

// ---------------- setup: biases, initial hidden, counters, FMA2 canary ----------------
__global__ void setup_kernel(const float* __restrict__ h0,
                             const float* __restrict__ bih0, const float* __restrict__ bhh0,
                             const float* __restrict__ bih1, const float* __restrict__ bhh1)
{
    int i0 = blockIdx.x * blockDim.x + threadIdx.x;
    if (i0 == 0) {
        // canary: asymmetric lanes catch lane-swap, lane-dup, or demotion bugs
        ull d1 = fma2(pack2(2.f, 3.f), pack2(5.f, 7.f), pack2(11.f, 13.f));   // (21, 34)
        ull d2 = fma2(pack2(-1.5f, 0.25f), pack2(4.f, -8.f), pack2(0.5f, 1.f)); // (-5.5, -1)
        int ok = (lo32(d1) == 21.f) && (hi32(d1) == 34.f) &&
                 (lo32(d2) == -5.5f) && (hi32(d2) == -1.f);
        g_use2 = ok;
    }
    if (i0 < NH) {
        g_bias0[i0] = bih0[i0] + bhh0[i0];
        g_bias1[i0] = bih1[i0] + bhh1[i0];
    }
    if (i0 < TT * 4) { g_ctr0[i0] = 0; g_ctr1[i0] = 0; }
    int stride = gridDim.x * blockDim.x;
    for (int idx = i0; idx < BB * NH; idx += stride) {
        int b = idx >> 10;
        int n = idx & (NH - 1);
        int d = n >> 9;
        int j = n & (HH - 1);
        g_hi0[idx] = h0[(size_t)(d * BB + b) * HH + j];
        g_hi1[idx] = h0[(size_t)((2 + d) * BB + b) * HH + j];
    }
}

// ---------------- big GEMM: 128x128 tile, 8x8/thread, dual path ----------------
// AMODE 0: A row-major [M][K]. AMODE 1: A is x[B,T,IN], row m=t*B+b -> x + (b*T+t)*K.
// B staged duplicated as (w,w) float2 (serves both paths).
template<int AMODE>
__global__ void __launch_bounds__(256) gemm_big(
    const float* __restrict__ A, const float* __restrict__ W,
    const float* __restrict__ bias, float* __restrict__ C,
    int M, int N, int K)
{
    __shared__ float  sA[16][132];
    __shared__ float2 sBd[16][132];
    const int m0  = blockIdx.y * 128;
    const int n0  = blockIdx.x * 128;
    const int tid = threadIdx.x;
    const int lk  = tid & 15;
    const int lr  = tid >> 4;
    const int tx  = tid & 15;
    const int ty  = tid >> 4;
    const bool use2 = (g_use2 != 0);

    if (use2) {
        // -------- FMA2 path: m-pairs packed, B lanes pre-duplicated --------
        ull acc2[4][8];
#pragma unroll
        for (int p = 0; p < 4; p++)
#pragma unroll
            for (int j = 0; j < 8; j++) acc2[p][j] = 0ull;

        for (int k0 = 0; k0 < K; k0 += 16) {
#pragma unroll
            for (int r = 0; r < 8; r++) {
                int m = m0 + lr + r * 16;
                const float* arow;
                if (AMODE == 1) arow = A + ((size_t)((m & (BB - 1)) * TT + (m >> 7))) * K;
                else            arow = A + (size_t)m * K;
                sA[lk][lr + r * 16] = arow[k0 + lk];
                float w = W[(size_t)(n0 + lr + r * 16) * K + k0 + lk];
                sBd[lk][lr + r * 16] = make_float2(w, w);
            }
            __syncthreads();
#pragma unroll
            for (int kk = 0; kk < 16; kk++) {
                ulonglong2 aA = *(const ulonglong2*)&sA[kk][tx * 4];
                ulonglong2 aB = *(const ulonglong2*)&sA[kk][64 + tx * 4];
                ulonglong2 b0 = *(const ulonglong2*)&sBd[kk][ty * 4];
                ulonglong2 b1 = *(const ulonglong2*)&sBd[kk][ty * 4 + 2];
                ulonglong2 b2 = *(const ulonglong2*)&sBd[kk][64 + ty * 4];
                ulonglong2 b3 = *(const ulonglong2*)&sBd[kk][64 + ty * 4 + 2];
                ull ap[4] = {aA.x, aA.y, aB.x, aB.y};
                ull bj[8] = {b0.x, b0.y, b1.x, b1.y, b2.x, b2.y, b3.x, b3.y};
#pragma unroll
                for (int p = 0; p < 4; p++)
#pragma unroll
                    for (int j = 0; j < 8; j++)
                        acc2[p][j] = fma2(ap[p], bj[j], acc2[p][j]);
            }
            __syncthreads();
        }

#pragma unroll
        for (int p = 0; p < 4; p++) {
            int mb = m0 + ((p >> 1) ? 64 : 0) + tx * 4 + (p & 1) * 2;
#pragma unroll
            for (int h = 0; h < 2; h++) {
                int m = mb + h;
#pragma unroll
                for (int jh = 0; jh < 2; jh++) {
                    int n = n0 + jh * 64 + ty * 4;
                    float4 v;
                    v.x = (h ? hi32(acc2[p][jh*4+0]) : lo32(acc2[p][jh*4+0])) + bias[n + 0];
                    v.y = (h ? hi32(acc2[p][jh*4+1]) : lo32(acc2[p][jh*4+1])) + bias[n + 1];
                    v.z = (h ? hi32(acc2[p][jh*4+2]) : lo32(acc2[p][jh*4+2])) + bias[n + 2];
                    v.w = (h ? hi32(acc2[p][jh*4+3]) : lo32(acc2[p][jh*4+3])) + bias[n + 3];
                    *(float4*)&C[(size_t)m * N + n] = v;
                }
            }
        }
    } else {
        // -------- scalar path (R3-proven) --------
        float acc[8][8];
#pragma unroll
        for (int i = 0; i < 8; i++)
#pragma unroll
            for (int j = 0; j < 8; j++) acc[i][j] = 0.f;

        for (int k0 = 0; k0 < K; k0 += 16) {
#pragma unroll
            for (int r = 0; r < 8; r++) {
                int m = m0 + lr + r * 16;
                const float* arow;
                if (AMODE == 1) arow = A + ((size_t)((m & (BB - 1)) * TT + (m >> 7))) * K;
                else            arow = A + (size_t)m * K;
                sA[lk][lr + r * 16] = arow[k0 + lk];
                float w = W[(size_t)(n0 + lr + r * 16) * K + k0 + lk];
                sBd[lk][lr + r * 16] = make_float2(w, w);
            }
            __syncthreads();
#pragma unroll
            for (int kk = 0; kk < 16; kk++) {
                float4 a0 = *(const float4*)&sA[kk][tx * 4];
                float4 a1 = *(const float4*)&sA[kk][64 + tx * 4];
                float4 p0 = *(const float4*)&sBd[kk][ty * 4];       // (w0,w0,w1,w1)
                float4 p1 = *(const float4*)&sBd[kk][ty * 4 + 2];   // (w2,w2,w3,w3)
                float4 p2 = *(const float4*)&sBd[kk][64 + ty * 4];
                float4 p3 = *(const float4*)&sBd[kk][64 + ty * 4 + 2];
                float av[8] = {a0.x, a0.y, a0.z, a0.w, a1.x, a1.y, a1.z, a1.w};
                float bv[8] = {p0.x, p0.z, p1.x, p1.z, p2.x, p2.z, p3.x, p3.z};
#pragma unroll
                for (int i = 0; i < 8; i++)
#pragma unroll
                    for (int j = 0; j < 8; j++) acc[i][j] += av[i] * bv[j];
            }
            __syncthreads();
        }

#pragma unroll
        for (int ih = 0; ih < 2; ih++)
#pragma unroll
        for (int i = 0; i < 4; i++) {
            int m = m0 + ih * 64 + tx * 4 + i;
#pragma unroll
            for (int jh = 0; jh < 2; jh++) {
                int n = n0 + jh * 64 + ty * 4;
                float4 v;
                v.x = acc[ih * 4 + i][jh * 4 + 0] + bias[n + 0];
                v.y = acc[ih * 4 + i][jh * 4 + 1] + bias[n + 1];
                v.z = acc[ih * 4 + i][jh * 4 + 2] + bias[n + 2];
                v.w = acc[ih * 4 + i][jh * 4 + 3] + bias[n + 3];
                *(float4*)&C[(size_t)m * N + n] = v;
            }
        }
    }
}

// ---------------- small GEMM for head: 64x64 tile ----------------
template<int ACT>
__global__ void __launch_bounds__(256) gemm_bias(
    const float* __restrict__ A, const float* __restrict__ W,
    const float* __restrict__ bias, float* __restrict__ C,
    int M, int N, int K)
{
    __shared__ float sA[16][68];
    __shared__ float sB[16][68];
    const int m0  = blockIdx.y * 64;
    const int n0  = blockIdx.x * 64;
    const int tid = threadIdx.x;
    const int lk  = tid & 15;
    const int lr  = tid >> 4;
    const int tx  = tid & 15;
    const int ty  = tid >> 4;

    float acc[4][4];
#pragma unroll
    for (int i = 0; i < 4; i++)
#pragma unroll
        for (int j = 0; j < 4; j++) acc[i][j] = 0.f;

    for (int k0 = 0; k0 < K; k0 += 16) {
#pragma unroll
        for (int r = 0; r < 4; r++) {
            int m = m0 + lr + r * 16;
            sA[lk][lr + r * 16] = A[(size_t)m * K + k0 + lk];
            sB[lk][lr + r * 16] = W[(size_t)(n0 + lr + r * 16) * K + k0 + lk];
        }
        __syncthreads();
#pragma unroll
        for (int kk = 0; kk < 16; kk++) {
            float4 a4 = *(const float4*)&sA[kk][tx * 4];
            float4 b4 = *(const float4*)&sB[kk][ty * 4];
            float av[4] = {a4.x, a4.y, a4.z, a4.w};
            float bv[4] = {b4.x, b4.y, b4.z, b4.w};
#pragma unroll
            for (int i = 0; i < 4; i++)
#pragma unroll
                for (int j = 0; j < 4; j++) acc[i][j] += av[i] * bv[j];
        }
        __syncthreads();
    }

#pragma unroll
    for (int i = 0; i < 4; i++) {
        int m = m0 + tx * 4 + i;
        float4 v;
        float* vp = (float*)&v;
#pragma unroll
        for (int j = 0; j < 4; j++) {
            float t = acc[i][j] + bias[n0 + ty * 4 + j];
            if (ACT == 2) t = 1.f / (1.f + expf(-t));
            vp[j] = t;
        }
        *(float4*)&C[(size_t)m * N + n0 + ty * 4] = v;
    }
}

// ---------------- persistent recurrence (dual path, group-scoped barrier) ----------------
// 128 CTAs x 128 threads. CTA tile: 64 b x 16 n; thread: 4 b (tx+16i) x 2 n.
// Dependencies factor into 4 independent groups of 32 CTAs: (bt, direction).
template<int LAYER0>
__global__ void __launch_bounds__(128, 1) rnn_layer(
    const float* __restrict__ P, const float* __restrict__ hinit,
    const float* __restrict__ Whh, float* __restrict__ Hbuf,
    float* __restrict__ pA, float* __restrict__ pB, int* __restrict__ ctr)
{
    extern __shared__ float smem[];
    float4* sW4 = (float4*)smem;                 // [16][SROW]
    float4* sH4 = ((float4*)smem) + 16 * SROW;   // [64][SROW]

    const int tid   = threadIdx.x;
    const int bid   = blockIdx.x;
    const int nt    = bid & 63;
    const int bt    = bid >> 6;
    const int nBase = nt * 16;
    const int b0    = bt * 64;
    const int dir   = nt >> 5;                  // 0 = fwd cols, 1 = bwd cols
    const int gid   = bt * 2 + dir;             // sync group id (32 CTAs each)
    const int kOff4 = dir ? (HH >> 2) : 0;
    const int tx    = tid & 15;
    const int ty    = tid >> 4;
    const bool use2 = (g_use2 != 0);

    const float4* W4 = (const float4*)Whh;
#pragma unroll
    for (int n = 0; n < 16; n++)
        sW4[n * SROW + tid] = W4[(size_t)(nBase + n) * 128 + tid];
    __syncthreads();

    const int n = nBase + ty * 2;

    for (int t = 0; t < TT; t++) {
        const float* Hin;
        float* Hout;
        if (LAYER0) {
            Hin  = (t == 0) ? hinit : (Hbuf + (size_t)(t - 1) * BB * NH);
            Hout = Hbuf + (size_t)t * BB * NH;
        } else {
            Hin  = (t == 0) ? hinit : (((t - 1) & 1) ? pB : pA);
            Hout = (t & 1) ? pB : pA;
        }

        // prefetch this step's P tile into registers
        const float* Pt = P + (size_t)t * BB * NH;
        float2 pv[4];
#pragma unroll
        for (int i = 0; i < 4; i++)
            pv[i] = *(const float2*)&Pt[(size_t)(b0 + tx + 16 * i) * NH + n];

        // stage Hin tile: 64 rows x 128 float4
        const float4* Hin4 = (const float4*)Hin;
#pragma unroll 16
        for (int b = 0; b < 64; b++)
            sH4[b * SROW + tid] = __ldcg(&Hin4[(size_t)(b0 + b) * 256 + kOff4 + tid]);
        __syncthreads();

        float res[4][2];
        if (use2) {
            ull acc2[4][2];
#pragma unroll
            for (int i = 0; i < 4; i++) { acc2[i][0] = 0ull; acc2[i][1] = 0ull; }
            const ulonglong2* w0p = (const ulonglong2*)&sW4[(ty * 2) * SROW];
            const ulonglong2* w1p = (const ulonglong2*)&sW4[(ty * 2 + 1) * SROW];
#pragma unroll 2
            for (int kq = 0; kq < 128; kq++) {
                ulonglong2 w0 = w0p[kq];
                ulonglong2 w1 = w1p[kq];
#pragma unroll
                for (int i = 0; i < 4; i++) {
                    ulonglong2 a = *(const ulonglong2*)&sH4[(tx + 16 * i) * SROW + kq];
                    acc2[i][0] = fma2(a.x, w0.x, acc2[i][0]);
                    acc2[i][0] = fma2(a.y, w0.y, acc2[i][0]);
                    acc2[i][1] = fma2(a.x, w1.x, acc2[i][1]);
                    acc2[i][1] = fma2(a.y, w1.y, acc2[i][1]);
                }
            }
#pragma unroll
            for (int i = 0; i < 4; i++) {
                res[i][0] = lo32(acc2[i][0]) + hi32(acc2[i][0]);
                res[i][1] = lo32(acc2[i][1]) + hi32(acc2[i][1]);
            }
        } else {
            float acc[4][2];
#pragma unroll
            for (int i = 0; i < 4; i++) { acc[i][0] = 0.f; acc[i][1] = 0.f; }
            const float4* w0p = &sW4[(ty * 2) * SROW];
            const float4* w1p = &sW4[(ty * 2 + 1) * SROW];
#pragma unroll 2
            for (int kq = 0; kq < 128; kq++) {
                float4 w0 = w0p[kq];
                float4 w1 = w1p[kq];
#pragma unroll
                for (int i = 0; i < 4; i++) {
                    float4 a = sH4[(tx + 16 * i) * SROW + kq];
                    acc[i][0] += a.x * w0.x; acc[i][0] += a.y * w0.y;
                    acc[i][0] += a.z * w0.z; acc[i][0] += a.w * w0.w;
                    acc[i][1] += a.x * w1.x; acc[i][1] += a.y * w1.y;
                    acc[i][1] += a.z * w1.z; acc[i][1] += a.w * w1.w;
                }
            }
#pragma unroll
            for (int i = 0; i < 4; i++) { res[i][0] = acc[i][0]; res[i][1] = acc[i][1]; }
        }

#pragma unroll
        for (int i = 0; i < 4; i++) {
            int b = b0 + tx + 16 * i;
            float2 o;
            o.x = fmaxf(res[i][0] + pv[i].x, 0.f);
            o.y = fmaxf(res[i][1] + pv[i].y, 0.f);
            __stcg((float2*)&Hout[(size_t)b * NH + n], o);
        }

        __syncthreads();
        __threadfence();
        if (tid == 0) {
            int idx = t * 4 + gid;
            atomicAdd(&ctr[idx], 1);
            while (((volatile int*)ctr)[idx] < GNUM) __nanosleep(32);
        }
        __syncthreads();
        __threadfence();
    }
}

// ---------------- BatchNorm1d (training, biased var) + ReLU ----------------
__global__ void bn_relu(const float* __restrict__ V, const float* __restrict__ gw,
                        const float* __restrict__ bw, float* __restrict__ Y, int cols)
{
    int c = blockIdx.x;
    int t = threadIdx.x;
    float v = V[(size_t)t * cols + c];
    float s = v, ss = v * v;
#pragma unroll
    for (int o = 16; o > 0; o >>= 1) {
        s  += __shfl_down_sync(0xffffffffu, s,  o);
        ss += __shfl_down_sync(0xffffffffu, ss, o);
    }
    __shared__ float rs[4], rq[4];
    if ((t & 31) == 0) { rs[t >> 5] = s; rq[t >> 5] = ss; }
    __syncthreads();
    float S = rs[0] + rs[1] + rs[2] + rs[3];
    float Q = rq[0] + rq[1] + rq[2] + rq[3];
    float mean = S * (1.f / BB);
    float var  = Q * (1.f / BB) - mean * mean;
    float y = (v - mean) * rsqrtf(var + EPSF) * gw[c] + bw[c];
    Y[(size_t)t * cols + c] = fmaxf(y, 0.f);
}

// ---------------- launch ----------------
extern "C" void kernel_launch(void* const* d_in, const int* in_sizes, int n_in,
                              void* d_out, int out_size)
{
    (void)in_sizes; (void)n_in; (void)out_size;
    const float* x     = (const float*)d_in[0];
    const float* h0    = (const float*)d_in[1];
    const float* W_ih0 = (const float*)d_in[2];
    const float* W_hh0 = (const float*)d_in[3];
    const float* b_ih0 = (const float*)d_in[4];
    const float* b_hh0 = (const float*)d_in[5];
    const float* W_ih1 = (const float*)d_in[6];
    const float* W_hh1 = (const float*)d_in[7];
    const float* b_ih1 = (const float*)d_in[8];
    const float* b_hh1 = (const float*)d_in[9];
    const float* bn1_g = (const float*)d_in[10];
    const float* bn1_b = (const float*)d_in[11];
    const float* fc1_W = (const float*)d_in[12];
    const float* fc1_b = (const float*)d_in[13];
    const float* bn2_g = (const float*)d_in[14];
    const float* bn2_b = (const float*)d_in[15];
    const float* fc2_W = (const float*)d_in[16];
    const float* fc2_b = (const float*)d_in[17];
    float* out = (float*)d_out;

    float *P, *H0p, *hi0, *hi1, *h1a, *h1b, *bs0, *bs1, *y1, *z;
    int *c0, *c1;
    cudaGetSymbolAddress((void**)&P,   g_P);
    cudaGetSymbolAddress((void**)&H0p, g_H0buf);
    cudaGetSymbolAddress((void**)&hi0, g_hi0);
    cudaGetSymbolAddress((void**)&hi1, g_hi1);
    cudaGetSymbolAddress((void**)&h1a, g_h1a);
    cudaGetSymbolAddress((void**)&h1b, g_h1b);
    cudaGetSymbolAddress((void**)&bs0, g_bias0);
    cudaGetSymbolAddress((void**)&bs1, g_bias1);
    cudaGetSymbolAddress((void**)&y1,  g_y1);
    cudaGetSymbolAddress((void**)&z,   g_z);
    cudaGetSymbolAddress((void**)&c0,  g_ctr0);
    cudaGetSymbolAddress((void**)&c1,  g_ctr1);

    cudaFuncSetAttribute(rnn_layer<1>, cudaFuncAttributeMaxDynamicSharedMemorySize, RNN_SMEM);
    cudaFuncSetAttribute(rnn_layer<0>, cudaFuncAttributeMaxDynamicSharedMemorySize, RNN_SMEM);

    // 0) canary + biases + initial hidden + barrier counters
    setup_kernel<<<256, 256>>>(h0, b_ih0, b_hh0, b_ih1, b_hh1);

    // 1) P0 = x @ Wih0^T + biases   (34.4 GMAC)
    gemm_big<1><<<dim3(NH / 128, M_BIG / 128), 256>>>(x, W_ih0, bs0, P, M_BIG, NH, IND);

    // 2) layer-0 recurrence (68.7 GMAC, all timesteps stored)
    rnn_layer<1><<<NCTA, 128, RNN_SMEM>>>(P, hi0, W_hh0, H0p, nullptr, nullptr, c0);

    // 3) P1 = H0 @ Wih1^T + biases  (137.4 GMAC)
    gemm_big<0><<<dim3(NH / 128, M_BIG / 128), 256>>>(H0p, W_ih1, bs1, P, M_BIG, NH, NH);

    // 4) layer-1 recurrence; final state lands in h1b (t=1023 odd)
    rnn_layer<0><<<NCTA, 128, RNN_SMEM>>>(P, hi1, W_hh1, nullptr, h1a, h1b, c1);

    // 5) head
    bn_relu<<<NH, 128>>>(h1b, bn1_g, bn1_b, y1, NH);
    gemm_bias<0><<<dim3(FC1N / 64, BB / 64), 256>>>(y1, fc1_W, fc1_b, z, BB, FC1N, NH);
    bn_relu<<<FC1N, 128>>>(z, bn2_g, bn2_b, z, FC1N);
    gemm_bias<2><<<dim3(OUTN / 64, BB / 64), 256>>>(z, fc2_W, fc2_b, out, BB, OUTN, FC1N);
}

// round 6
// speedup vs baseline: 1.0885x; 1.0885x over previous
#include <cuda_runtime.h>
#include <math.h>

#define BB    128
#define TT    1024
#define IND   256
#define HH    512
#define NH    1024          // 2*H
#define FC1N  2048
#define OUTN  128
#define EPSF  1e-5f

#define M_BIG (TT * BB)
#define NCTA  128           // persistent recurrence grid
#define GNUM  32            // CTAs per independent sync group (bt x direction)
#define SROW  129           // smem row stride in float4 (odd -> bank-group step 1)
#define RNN_SMEM ((16 + 64) * SROW * 16)   // 165,120 bytes

typedef unsigned long long ull;

// packed dual-fp32 fma (f32x2). Each 32-bit lane is an exact fp32 fma (verified R5).
__device__ __forceinline__ ull fma2(ull a, ull b, ull c) {
    ull d;
    asm("fma.rn.f32x2 %0, %1, %2, %3;" : "=l"(d) : "l"(a), "l"(b), "l"(c));
    return d;
}
__device__ __forceinline__ float lo32(ull v) { return __uint_as_float((unsigned)v); }
__device__ __forceinline__ float hi32(ull v) { return __uint_as_float((unsigned)(v >> 32)); }

// ---------------- device scratch ----------------
__device__ float g_P[TT * BB * NH];      // 512 MB: P0 then P1
__device__ float g_H0buf[TT * BB * NH];  // 512 MB: all layer-0 hidden states
__device__ float g_hi0[BB * NH];
__device__ float g_hi1[BB * NH];
__device__ float g_h1a[BB * NH];
__device__ float g_h1b[BB * NH];
__device__ float g_bias0[NH];
__device__ float g_bias1[NH];
__device__ float g_y1[BB * NH];
__device__ float g_z[BB * FC1N];
__device__ int   g_ctr0[TT * 4];         // per-step, per-group barrier counters
__device__ int   g_ctr1[TT * 4];

// ---------------- setup: biases, initial hidden, counters ----------------
__global__ void setup_kernel(const float* __restrict__ h0,
                             const float* __restrict__ bih0, const float* __restrict__ bhh0,
                             const float* __restrict__ bih1, const float* __restrict__ bhh1)
{
    int i0 = blockIdx.x * blockDim.x + threadIdx.x;
    if (i0 < NH) {
        g_bias0[i0] = bih0[i0] + bhh0[i0];
        g_bias1[i0] = bih1[i0] + bhh1[i0];
    }
    if (i0 < TT * 4) { g_ctr0[i0] = 0; g_ctr1[i0] = 0; }
    int stride = gridDim.x * blockDim.x;
    for (int idx = i0; idx < BB * NH; idx += stride) {
        int b = idx >> 10;
        int n = idx & (NH - 1);
        int d = n >> 9;
        int j = n & (HH - 1);
        g_hi0[idx] = h0[(size_t)(d * BB + b) * HH + j];
        g_hi1[idx] = h0[(size_t)((2 + d) * BB + b) * HH + j];
    }
}

// ---------------- big GEMM: 128x128 tile, 8x8/thread, FFMA2 over m-pairs ----------------
// AMODE 0: A row-major [M][K]. AMODE 1: A is x[B,T,IN], row m=t*B+b -> x + (b*T+t)*K.
// B staged duplicated as (w,w) float2 so m-pair FMA2 needs no register packing.
// __launch_bounds__(256, 2): cap regs at 128 -> 2 CTAs/SM (the R5 regression fix).
template<int AMODE>
__global__ void __launch_bounds__(256, 2) gemm_big(
    const float* __restrict__ A, const float* __restrict__ W,
    const float* __restrict__ bias, float* __restrict__ C,
    int M, int N, int K)
{
    __shared__ float  sA[16][132];
    __shared__ float2 sBd[16][132];
    const int m0  = blockIdx.y * 128;
    const int n0  = blockIdx.x * 128;
    const int tid = threadIdx.x;
    const int lk  = tid & 15;
    const int lr  = tid >> 4;
    const int tx  = tid & 15;
    const int ty  = tid >> 4;

    // acc2[p][j]: p = m-pair (0:{tx*4+0,1} 1:{+2,3} 2:{64+tx*4+0,1} 3:{+2,3}), j = n 0..7
    ull acc2[4][8];
#pragma unroll
    for (int p = 0; p < 4; p++)
#pragma unroll
        for (int j = 0; j < 8; j++) acc2[p][j] = 0ull;

    for (int k0 = 0; k0 < K; k0 += 16) {
#pragma unroll
        for (int r = 0; r < 8; r++) {
            int m = m0 + lr + r * 16;
            const float* arow;
            if (AMODE == 1) arow = A + ((size_t)((m & (BB - 1)) * TT + (m >> 7))) * K;
            else            arow = A + (size_t)m * K;
            sA[lk][lr + r * 16] = arow[k0 + lk];
            float w = W[(size_t)(n0 + lr + r * 16) * K + k0 + lk];
            sBd[lk][lr + r * 16] = make_float2(w, w);
        }
        __syncthreads();
#pragma unroll
        for (int kk = 0; kk < 16; kk++) {
            ulonglong2 aA = *(const ulonglong2*)&sA[kk][tx * 4];
            ulonglong2 aB = *(const ulonglong2*)&sA[kk][64 + tx * 4];
            ulonglong2 b0 = *(const ulonglong2*)&sBd[kk][ty * 4];
            ulonglong2 b1 = *(const ulonglong2*)&sBd[kk][ty * 4 + 2];
            ulonglong2 b2 = *(const ulonglong2*)&sBd[kk][64 + ty * 4];
            ulonglong2 b3 = *(const ulonglong2*)&sBd[kk][64 + ty * 4 + 2];
            ull ap[4] = {aA.x, aA.y, aB.x, aB.y};
            ull bj[8] = {b0.x, b0.y, b1.x, b1.y, b2.x, b2.y, b3.x, b3.y};
#pragma unroll
            for (int p = 0; p < 4; p++)
#pragma unroll
                for (int j = 0; j < 8; j++)
                    acc2[p][j] = fma2(ap[p], bj[j], acc2[p][j]);
        }
        __syncthreads();
    }

#pragma unroll
    for (int p = 0; p < 4; p++) {
        int mb = m0 + ((p >> 1) ? 64 : 0) + tx * 4 + (p & 1) * 2;
#pragma unroll
        for (int h = 0; h < 2; h++) {
            int m = mb + h;
#pragma unroll
            for (int jh = 0; jh < 2; jh++) {
                int n = n0 + jh * 64 + ty * 4;
                float4 v;
                v.x = (h ? hi32(acc2[p][jh*4+0]) : lo32(acc2[p][jh*4+0])) + bias[n + 0];
                v.y = (h ? hi32(acc2[p][jh*4+1]) : lo32(acc2[p][jh*4+1])) + bias[n + 1];
                v.z = (h ? hi32(acc2[p][jh*4+2]) : lo32(acc2[p][jh*4+2])) + bias[n + 2];
                v.w = (h ? hi32(acc2[p][jh*4+3]) : lo32(acc2[p][jh*4+3])) + bias[n + 3];
                *(float4*)&C[(size_t)m * N + n] = v;
            }
        }
    }
}

// ---------------- small GEMM for head: 64x64 tile ----------------
template<int ACT>
__global__ void __launch_bounds__(256) gemm_bias(
    const float* __restrict__ A, const float* __restrict__ W,
    const float* __restrict__ bias, float* __restrict__ C,
    int M, int N, int K)
{
    __shared__ float sA[16][68];
    __shared__ float sB[16][68];
    const int m0  = blockIdx.y * 64;
    const int n0  = blockIdx.x * 64;
    const int tid = threadIdx.x;
    const int lk  = tid & 15;
    const int lr  = tid >> 4;
    const int tx  = tid & 15;
    const int ty  = tid >> 4;

    float acc[4][4];
#pragma unroll
    for (int i = 0; i < 4; i++)
#pragma unroll
        for (int j = 0; j < 4; j++) acc[i][j] = 0.f;

    for (int k0 = 0; k0 < K; k0 += 16) {
#pragma unroll
        for (int r = 0; r < 4; r++) {
            int m = m0 + lr + r * 16;
            sA[lk][lr + r * 16] = A[(size_t)m * K + k0 + lk];
            sB[lk][lr + r * 16] = W[(size_t)(n0 + lr + r * 16) * K + k0 + lk];
        }
        __syncthreads();
#pragma unroll
        for (int kk = 0; kk < 16; kk++) {
            float4 a4 = *(const float4*)&sA[kk][tx * 4];
            float4 b4 = *(const float4*)&sB[kk][ty * 4];
            float av[4] = {a4.x, a4.y, a4.z, a4.w};
            float bv[4] = {b4.x, b4.y, b4.z, b4.w};
#pragma unroll
            for (int i = 0; i < 4; i++)
#pragma unroll
                for (int j = 0; j < 4; j++) acc[i][j] += av[i] * bv[j];
        }
        __syncthreads();
    }

#pragma unroll
    for (int i = 0; i < 4; i++) {
        int m = m0 + tx * 4 + i;
        float4 v;
        float* vp = (float*)&v;
#pragma unroll
        for (int j = 0; j < 4; j++) {
            float t = acc[i][j] + bias[n0 + ty * 4 + j];
            if (ACT == 2) t = 1.f / (1.f + expf(-t));
            vp[j] = t;
        }
        *(float4*)&C[(size_t)m * N + n0 + ty * 4] = v;
    }
}

// ---------------- persistent recurrence (FFMA2, group-scoped barrier) ----------------
// 128 CTAs x 128 threads. CTA tile: 64 b x 16 n; thread: 4 b (tx+16i) x 2 n.
// Dependencies factor into 4 independent groups of 32 CTAs: (bt, direction).
template<int LAYER0>
__global__ void __launch_bounds__(128, 1) rnn_layer(
    const float* __restrict__ P, const float* __restrict__ hinit,
    const float* __restrict__ Whh, float* __restrict__ Hbuf,
    float* __restrict__ pA, float* __restrict__ pB, int* __restrict__ ctr)
{
    extern __shared__ float smem[];
    float4* sW4 = (float4*)smem;                 // [16][SROW]
    float4* sH4 = ((float4*)smem) + 16 * SROW;   // [64][SROW]

    const int tid   = threadIdx.x;
    const int bid   = blockIdx.x;
    const int nt    = bid & 63;
    const int bt    = bid >> 6;
    const int nBase = nt * 16;
    const int b0    = bt * 64;
    const int dir   = nt >> 5;                  // 0 = fwd cols, 1 = bwd cols
    const int gid   = bt * 2 + dir;             // sync group id (32 CTAs each)
    const int kOff4 = dir ? (HH >> 2) : 0;
    const int tx    = tid & 15;
    const int ty    = tid >> 4;

    const float4* W4 = (const float4*)Whh;
#pragma unroll
    for (int n = 0; n < 16; n++)
        sW4[n * SROW + tid] = W4[(size_t)(nBase + n) * 128 + tid];
    __syncthreads();

    const int n = nBase + ty * 2;

    for (int t = 0; t < TT; t++) {
        const float* Hin;
        float* Hout;
        if (LAYER0) {
            Hin  = (t == 0) ? hinit : (Hbuf + (size_t)(t - 1) * BB * NH);
            Hout = Hbuf + (size_t)t * BB * NH;
        } else {
            Hin  = (t == 0) ? hinit : (((t - 1) & 1) ? pB : pA);
            Hout = (t & 1) ? pB : pA;
        }

        // prefetch this step's P tile into registers (overlaps staging)
        const float* Pt = P + (size_t)t * BB * NH;
        float2 pv[4];
#pragma unroll
        for (int i = 0; i < 4; i++)
            pv[i] = *(const float2*)&Pt[(size_t)(b0 + tx + 16 * i) * NH + n];

        // stage Hin tile: 64 rows x 128 float4 (consecutive-lane writes: conflict-free)
        const float4* Hin4 = (const float4*)Hin;
#pragma unroll 16
        for (int b = 0; b < 64; b++)
            sH4[b * SROW + tid] = __ldcg(&Hin4[(size_t)(b0 + b) * 256 + kOff4 + tid]);
        __syncthreads();

        // acc2[i][j]: k-even/odd partial sums packed in one f32x2 register
        ull acc2[4][2];
#pragma unroll
        for (int i = 0; i < 4; i++) { acc2[i][0] = 0ull; acc2[i][1] = 0ull; }

        const ulonglong2* w0p = (const ulonglong2*)&sW4[(ty * 2) * SROW];
        const ulonglong2* w1p = (const ulonglong2*)&sW4[(ty * 2 + 1) * SROW];
#pragma unroll 2
        for (int kq = 0; kq < 128; kq++) {
            ulonglong2 w0 = w0p[kq];   // pairs (k0,k1),(k2,k3)
            ulonglong2 w1 = w1p[kq];
#pragma unroll
            for (int i = 0; i < 4; i++) {
                ulonglong2 a = *(const ulonglong2*)&sH4[(tx + 16 * i) * SROW + kq];
                acc2[i][0] = fma2(a.x, w0.x, acc2[i][0]);
                acc2[i][0] = fma2(a.y, w0.y, acc2[i][0]);
                acc2[i][1] = fma2(a.x, w1.x, acc2[i][1]);
                acc2[i][1] = fma2(a.y, w1.y, acc2[i][1]);
            }
        }

#pragma unroll
        for (int i = 0; i < 4; i++) {
            int b = b0 + tx + 16 * i;
            float2 o;
            o.x = fmaxf(lo32(acc2[i][0]) + hi32(acc2[i][0]) + pv[i].x, 0.f);
            o.y = fmaxf(lo32(acc2[i][1]) + hi32(acc2[i][1]) + pv[i].y, 0.f);
            __stcg((float2*)&Hout[(size_t)b * NH + n], o);
        }

        __syncthreads();
        __threadfence();
        if (tid == 0) {
            int idx = t * 4 + gid;
            atomicAdd(&ctr[idx], 1);
            while (((volatile int*)ctr)[idx] < GNUM) __nanosleep(32);
        }
        __syncthreads();
        __threadfence();
    }
}

// ---------------- BatchNorm1d (training, biased var) + ReLU ----------------
__global__ void bn_relu(const float* __restrict__ V, const float* __restrict__ gw,
                        const float* __restrict__ bw, float* __restrict__ Y, int cols)
{
    int c = blockIdx.x;
    int t = threadIdx.x;
    float v = V[(size_t)t * cols + c];
    float s = v, ss = v * v;
#pragma unroll
    for (int o = 16; o > 0; o >>= 1) {
        s  += __shfl_down_sync(0xffffffffu, s,  o);
        ss += __shfl_down_sync(0xffffffffu, ss, o);
    }
    __shared__ float rs[4], rq[4];
    if ((t & 31) == 0) { rs[t >> 5] = s; rq[t >> 5] = ss; }
    __syncthreads();
    float S = rs[0] + rs[1] + rs[2] + rs[3];
    float Q = rq[0] + rq[1] + rq[2] + rq[3];
    float mean = S * (1.f / BB);
    float var  = Q * (1.f / BB) - mean * mean;
    float y = (v - mean) * rsqrtf(var + EPSF) * gw[c] + bw[c];
    Y[(size_t)t * cols + c] = fmaxf(y, 0.f);
}

// ---------------- launch ----------------
extern "C" void kernel_launch(void* const* d_in, const int* in_sizes, int n_in,
                              void* d_out, int out_size)
{
    (void)in_sizes; (void)n_in; (void)out_size;
    const float* x     = (const float*)d_in[0];
    const float* h0    = (const float*)d_in[1];
    const float* W_ih0 = (const float*)d_in[2];
    const float* W_hh0 = (const float*)d_in[3];
    const float* b_ih0 = (const float*)d_in[4];
    const float* b_hh0 = (const float*)d_in[5];
    const float* W_ih1 = (const float*)d_in[6];
    const float* W_hh1 = (const float*)d_in[7];
    const float* b_ih1 = (const float*)d_in[8];
    const float* b_hh1 = (const float*)d_in[9];
    const float* bn1_g = (const float*)d_in[10];
    const float* bn1_b = (const float*)d_in[11];
    const float* fc1_W = (const float*)d_in[12];
    const float* fc1_b = (const float*)d_in[13];
    const float* bn2_g = (const float*)d_in[14];
    const float* bn2_b = (const float*)d_in[15];
    const float* fc2_W = (const float*)d_in[16];
    const float* fc2_b = (const float*)d_in[17];
    float* out = (float*)d_out;

    float *P, *H0p, *hi0, *hi1, *h1a, *h1b, *bs0, *bs1, *y1, *z;
    int *c0, *c1;
    cudaGetSymbolAddress((void**)&P,   g_P);
    cudaGetSymbolAddress((void**)&H0p, g_H0buf);
    cudaGetSymbolAddress((void**)&hi0, g_hi0);
    cudaGetSymbolAddress((void**)&hi1, g_hi1);
    cudaGetSymbolAddress((void**)&h1a, g_h1a);
    cudaGetSymbolAddress((void**)&h1b, g_h1b);
    cudaGetSymbolAddress((void**)&bs0, g_bias0);
    cudaGetSymbolAddress((void**)&bs1, g_bias1);
    cudaGetSymbolAddress((void**)&y1,  g_y1);
    cudaGetSymbolAddress((void**)&z,   g_z);
    cudaGetSymbolAddress((void**)&c0,  g_ctr0);
    cudaGetSymbolAddress((void**)&c1,  g_ctr1);

    cudaFuncSetAttribute(rnn_layer<1>, cudaFuncAttributeMaxDynamicSharedMemorySize, RNN_SMEM);
    cudaFuncSetAttribute(rnn_layer<0>, cudaFuncAttributeMaxDynamicSharedMemorySize, RNN_SMEM);

    // 0) biases + initial hidden + barrier counters
    setup_kernel<<<256, 256>>>(h0, b_ih0, b_hh0, b_ih1, b_hh1);

    // 1) P0 = x @ Wih0^T + biases   (34.4 GMAC)
    gemm_big<1><<<dim3(NH / 128, M_BIG / 128), 256>>>(x, W_ih0, bs0, P, M_BIG, NH, IND);

    // 2) layer-0 recurrence (68.7 GMAC, all timesteps stored)
    rnn_layer<1><<<NCTA, 128, RNN_SMEM>>>(P, hi0, W_hh0, H0p, nullptr, nullptr, c0);

    // 3) P1 = H0 @ Wih1^T + biases  (137.4 GMAC)
    gemm_big<0><<<dim3(NH / 128, M_BIG / 128), 256>>>(H0p, W_ih1, bs1, P, M_BIG, NH, NH);

    // 4) layer-1 recurrence; final state lands in h1b (t=1023 odd)
    rnn_layer<0><<<NCTA, 128, RNN_SMEM>>>(P, hi1, W_hh1, nullptr, h1a, h1b, c1);

    // 5) head
    bn_relu<<<NH, 128>>>(h1b, bn1_g, bn1_b, y1, NH);
    gemm_bias<0><<<dim3(FC1N / 64, BB / 64), 256>>>(y1, fc1_W, fc1_b, z, BB, FC1N, NH);
    bn_relu<<<FC1N, 128>>>(z, bn2_g, bn2_b, z, FC1N);
    gemm_bias<2><<<dim3(OUTN / 64, BB / 64), 256>>>(z, fc2_W, fc2_b, out, BB, OUTN, FC1N);
}

// round 7
// speedup vs baseline: 1.1519x; 1.0583x over previous
#include <cuda_runtime.h>
#include <math.h>

#define BB    128
#define TT    1024
#define IND   256
#define HH    512
#define NH    1024          // 2*H
#define FC1N  2048
#define OUTN  128
#define EPSF  1e-5f

#define M_BIG (TT * BB)
#define NCTA  128           // persistent recurrence grid
#define GNUM  32            // CTAs per independent sync group (bt x direction)
#define SROW  129           // rnn smem row stride in float4
#define RNN_SMEM ((16 + 64) * SROW * 16)   // 165,120 bytes

typedef unsigned long long ull;

// packed dual-fp32 fma (f32x2); each lane is an exact fp32 fma (verified R5/R6).
__device__ __forceinline__ ull fma2(ull a, ull b, ull c) {
    ull d;
    asm("fma.rn.f32x2 %0, %1, %2, %3;" : "=l"(d) : "l"(a), "l"(b), "l"(c));
    return d;
}
__device__ __forceinline__ float lo32(ull v) { return __uint_as_float((unsigned)v); }
__device__ __forceinline__ float hi32(ull v) { return __uint_as_float((unsigned)(v >> 32)); }

// tf32 split: x ~= hi + lo, both tf32-valued (stored as f32 bit patterns)
__device__ __forceinline__ void tf32_split(float x, unsigned &hi, unsigned &lo) {
    unsigned h;
    asm("cvt.rna.tf32.f32 %0, %1;" : "=r"(h) : "f"(x));
    float rem = x - __uint_as_float(h);
    unsigned l;
    asm("cvt.rna.tf32.f32 %0, %1;" : "=r"(l) : "f"(rem));
    hi = h; lo = l;
}

// D += A(16x8,row) * B(8x8,col)  tf32 inputs, fp32 accum
__device__ __forceinline__ void mma8(float* d, const unsigned* a, const unsigned* b) {
    asm volatile(
        "mma.sync.aligned.m16n8k8.row.col.f32.tf32.tf32.f32 "
        "{%0,%1,%2,%3}, {%4,%5,%6,%7}, {%8,%9}, {%0,%1,%2,%3};"
        : "+f"(d[0]), "+f"(d[1]), "+f"(d[2]), "+f"(d[3])
        : "r"(a[0]), "r"(a[1]), "r"(a[2]), "r"(a[3]), "r"(b[0]), "r"(b[1]));
}

// ---------------- device scratch ----------------
__device__ float g_P[TT * BB * NH];      // 512 MB: P0 then P1
__device__ float g_H0buf[TT * BB * NH];  // 512 MB: all layer-0 hidden states
__device__ float g_hi0[BB * NH];
__device__ float g_hi1[BB * NH];
__device__ float g_h1a[BB * NH];
__device__ float g_h1b[BB * NH];
__device__ float g_bias0[NH];
__device__ float g_bias1[NH];
__device__ float g_y1[BB * NH];
__device__ float g_z[BB * FC1N];
__device__ int   g_ctr0[TT * 4];
__device__ int   g_ctr1[TT * 4];

// ---------------- setup ----------------
__global__ void setup_kernel(const float* __restrict__ h0,
                             const float* __restrict__ bih0, const float* __restrict__ bhh0,
                             const float* __restrict__ bih1, const float* __restrict__ bhh1)
{
    int i0 = blockIdx.x * blockDim.x + threadIdx.x;
    if (i0 < NH) {
        g_bias0[i0] = bih0[i0] + bhh0[i0];
        g_bias1[i0] = bih1[i0] + bhh1[i0];
    }
    if (i0 < TT * 4) { g_ctr0[i0] = 0; g_ctr1[i0] = 0; }
    int stride = gridDim.x * blockDim.x;
    for (int idx = i0; idx < BB * NH; idx += stride) {
        int b = idx >> 10;
        int n = idx & (NH - 1);
        int d = n >> 9;
        int j = n & (HH - 1);
        g_hi0[idx] = h0[(size_t)(d * BB + b) * HH + j];
        g_hi1[idx] = h0[(size_t)((2 + d) * BB + b) * HH + j];
    }
}

// ---------------- tensor-core GEMM (tf32x3): C[M,N] = A[M,K] * W[N,K]^T + bias ----------
// CTA 128x128, 256 threads (8 warps, 2x4 warp grid, 64x32 warp tile), BK=16.
// AMODE 0: A row-major. AMODE 1: A is x[B,T,IN], GEMM row m=t*B+b -> x + (b*T+t)*K.
#define SK 20   // smem row stride in 4B words (16 data + 4 pad; frag loads conflict-free)
template<int AMODE>
__global__ void __launch_bounds__(256) gemm_tc(
    const float* __restrict__ A, const float* __restrict__ W,
    const float* __restrict__ bias, float* __restrict__ C,
    int M, int N, int K)
{
    __shared__ unsigned sAh[128][SK];
    __shared__ unsigned sAl[128][SK];
    __shared__ unsigned sWh[128][SK];
    __shared__ unsigned sWl[128][SK];

    const int m0   = blockIdx.y * 128;
    const int n0   = blockIdx.x * 128;
    const int tid  = threadIdx.x;
    const int lane = tid & 31;
    const int warp = tid >> 5;
    const int wm   = (warp & 1) * 64;   // warp m-offset
    const int wn   = (warp >> 1) * 32;  // warp n-offset
    const int r    = lane >> 2;         // fragment row group
    const int q    = lane & 3;          // fragment col group

    // staging assignment: 2 threads per row, 8 cols each
    const int srow = tid >> 1;
    const int scg  = (tid & 1) * 8;

    float acc[4][4][4];
#pragma unroll
    for (int i = 0; i < 4; i++)
#pragma unroll
        for (int j = 0; j < 4; j++)
#pragma unroll
            for (int c = 0; c < 4; c++) acc[i][j][c] = 0.f;

    const float* arow;
    {
        int m = m0 + srow;
        if (AMODE == 1) arow = A + ((size_t)((m & (BB - 1)) * TT + (m >> 7))) * K;
        else            arow = A + (size_t)m * K;
    }
    const float* wrow = W + (size_t)(n0 + srow) * K;

    for (int k0 = 0; k0 < K; k0 += 16) {
        // ---- stage + split 128x16 of A and W ----
        float4 av0 = *(const float4*)&arow[k0 + scg];
        float4 av1 = *(const float4*)&arow[k0 + scg + 4];
        float4 wv0 = *(const float4*)&wrow[k0 + scg];
        float4 wv1 = *(const float4*)&wrow[k0 + scg + 4];
        const float* af = (const float*)&av0;
#pragma unroll
        for (int j = 0; j < 4; j++) tf32_split(af[j], sAh[srow][scg + j], sAl[srow][scg + j]);
        af = (const float*)&av1;
#pragma unroll
        for (int j = 0; j < 4; j++) tf32_split(af[j], sAh[srow][scg + 4 + j], sAl[srow][scg + 4 + j]);
        const float* wf = (const float*)&wv0;
#pragma unroll
        for (int j = 0; j < 4; j++) tf32_split(wf[j], sWh[srow][scg + j], sWl[srow][scg + j]);
        wf = (const float*)&wv1;
#pragma unroll
        for (int j = 0; j < 4; j++) tf32_split(wf[j], sWh[srow][scg + 4 + j], sWl[srow][scg + 4 + j]);
        __syncthreads();

        // ---- compute: 2 k8 chunks ----
#pragma unroll
        for (int kk = 0; kk < 16; kk += 8) {
            // B fragments for the 4 n-tiles
            unsigned bh[4][2], bl[4][2];
#pragma unroll
            for (int nt = 0; nt < 4; nt++) {
                int nn = wn + nt * 8 + r;
                bh[nt][0] = sWh[nn][kk + q];
                bh[nt][1] = sWh[nn][kk + q + 4];
                bl[nt][0] = sWl[nn][kk + q];
                bl[nt][1] = sWl[nn][kk + q + 4];
            }
#pragma unroll
            for (int mt = 0; mt < 4; mt++) {
                int mm = wm + mt * 16 + r;
                unsigned ah[4], al[4];
                ah[0] = sAh[mm][kk + q];     ah[1] = sAh[mm + 8][kk + q];
                ah[2] = sAh[mm][kk + q + 4]; ah[3] = sAh[mm + 8][kk + q + 4];
                al[0] = sAl[mm][kk + q];     al[1] = sAl[mm + 8][kk + q];
                al[2] = sAl[mm][kk + q + 4]; al[3] = sAl[mm + 8][kk + q + 4];
#pragma unroll
                for (int nt = 0; nt < 4; nt++) {
                    mma8(acc[mt][nt], ah, bh[nt]);
                    mma8(acc[mt][nt], ah, bl[nt]);
                    mma8(acc[mt][nt], al, bh[nt]);
                }
            }
        }
        __syncthreads();
    }

    // ---- epilogue: bias + store ----
#pragma unroll
    for (int mt = 0; mt < 4; mt++) {
#pragma unroll
        for (int nt = 0; nt < 4; nt++) {
            int n  = n0 + wn + nt * 8 + q * 2;
            int ml = m0 + wm + mt * 16 + r;
            float bx = bias[n], by = bias[n + 1];
            float2 o0 = make_float2(acc[mt][nt][0] + bx, acc[mt][nt][1] + by);
            float2 o1 = make_float2(acc[mt][nt][2] + bx, acc[mt][nt][3] + by);
            *(float2*)&C[(size_t)ml * N + n]       = o0;
            *(float2*)&C[(size_t)(ml + 8) * N + n] = o1;
        }
    }
}

// ---------------- small GEMM for head: 64x64 tile ----------------
template<int ACT>
__global__ void __launch_bounds__(256) gemm_bias(
    const float* __restrict__ A, const float* __restrict__ W,
    const float* __restrict__ bias, float* __restrict__ C,
    int M, int N, int K)
{
    __shared__ float sA[16][68];
    __shared__ float sB[16][68];
    const int m0  = blockIdx.y * 64;
    const int n0  = blockIdx.x * 64;
    const int tid = threadIdx.x;
    const int lk  = tid & 15;
    const int lr  = tid >> 4;
    const int tx  = tid & 15;
    const int ty  = tid >> 4;

    float acc[4][4];
#pragma unroll
    for (int i = 0; i < 4; i++)
#pragma unroll
        for (int j = 0; j < 4; j++) acc[i][j] = 0.f;

    for (int k0 = 0; k0 < K; k0 += 16) {
#pragma unroll
        for (int rr = 0; rr < 4; rr++) {
            int m = m0 + lr + rr * 16;
            sA[lk][lr + rr * 16] = A[(size_t)m * K + k0 + lk];
            sB[lk][lr + rr * 16] = W[(size_t)(n0 + lr + rr * 16) * K + k0 + lk];
        }
        __syncthreads();
#pragma unroll
        for (int kk = 0; kk < 16; kk++) {
            float4 a4 = *(const float4*)&sA[kk][tx * 4];
            float4 b4 = *(const float4*)&sB[kk][ty * 4];
            float av[4] = {a4.x, a4.y, a4.z, a4.w};
            float bv[4] = {b4.x, b4.y, b4.z, b4.w};
#pragma unroll
            for (int i = 0; i < 4; i++)
#pragma unroll
                for (int j = 0; j < 4; j++) acc[i][j] += av[i] * bv[j];
        }
        __syncthreads();
    }

#pragma unroll
    for (int i = 0; i < 4; i++) {
        int m = m0 + tx * 4 + i;
        float4 v;
        float* vp = (float*)&v;
#pragma unroll
        for (int j = 0; j < 4; j++) {
            float t = acc[i][j] + bias[n0 + ty * 4 + j];
            if (ACT == 2) t = 1.f / (1.f + expf(-t));
            vp[j] = t;
        }
        *(float4*)&C[(size_t)m * N + n0 + ty * 4] = v;
    }
}

// ---------------- persistent recurrence (FFMA2, group-scoped barrier) ----------------
template<int LAYER0>
__global__ void __launch_bounds__(128, 1) rnn_layer(
    const float* __restrict__ P, const float* __restrict__ hinit,
    const float* __restrict__ Whh, float* __restrict__ Hbuf,
    float* __restrict__ pA, float* __restrict__ pB, int* __restrict__ ctr)
{
    extern __shared__ float smem[];
    float4* sW4 = (float4*)smem;                 // [16][SROW]
    float4* sH4 = ((float4*)smem) + 16 * SROW;   // [64][SROW]

    const int tid   = threadIdx.x;
    const int bid   = blockIdx.x;
    const int nt    = bid & 63;
    const int bt    = bid >> 6;
    const int nBase = nt * 16;
    const int b0    = bt * 64;
    const int dir   = nt >> 5;
    const int gid   = bt * 2 + dir;
    const int kOff4 = dir ? (HH >> 2) : 0;
    const int tx    = tid & 15;
    const int ty    = tid >> 4;

    const float4* W4 = (const float4*)Whh;
#pragma unroll
    for (int n = 0; n < 16; n++)
        sW4[n * SROW + tid] = W4[(size_t)(nBase + n) * 128 + tid];
    __syncthreads();

    const int n = nBase + ty * 2;

    for (int t = 0; t < TT; t++) {
        const float* Hin;
        float* Hout;
        if (LAYER0) {
            Hin  = (t == 0) ? hinit : (Hbuf + (size_t)(t - 1) * BB * NH);
            Hout = Hbuf + (size_t)t * BB * NH;
        } else {
            Hin  = (t == 0) ? hinit : (((t - 1) & 1) ? pB : pA);
            Hout = (t & 1) ? pB : pA;
        }

        const float* Pt = P + (size_t)t * BB * NH;
        float2 pv[4];
#pragma unroll
        for (int i = 0; i < 4; i++)
            pv[i] = *(const float2*)&Pt[(size_t)(b0 + tx + 16 * i) * NH + n];

        const float4* Hin4 = (const float4*)Hin;
#pragma unroll 16
        for (int b = 0; b < 64; b++)
            sH4[b * SROW + tid] = __ldcg(&Hin4[(size_t)(b0 + b) * 256 + kOff4 + tid]);
        __syncthreads();

        ull acc2[4][2];
#pragma unroll
        for (int i = 0; i < 4; i++) { acc2[i][0] = 0ull; acc2[i][1] = 0ull; }

        const ulonglong2* w0p = (const ulonglong2*)&sW4[(ty * 2) * SROW];
        const ulonglong2* w1p = (const ulonglong2*)&sW4[(ty * 2 + 1) * SROW];
#pragma unroll 2
        for (int kq = 0; kq < 128; kq++) {
            ulonglong2 w0 = w0p[kq];
            ulonglong2 w1 = w1p[kq];
#pragma unroll
            for (int i = 0; i < 4; i++) {
                ulonglong2 a = *(const ulonglong2*)&sH4[(tx + 16 * i) * SROW + kq];
                acc2[i][0] = fma2(a.x, w0.x, acc2[i][0]);
                acc2[i][0] = fma2(a.y, w0.y, acc2[i][0]);
                acc2[i][1] = fma2(a.x, w1.x, acc2[i][1]);
                acc2[i][1] = fma2(a.y, w1.y, acc2[i][1]);
            }
        }

#pragma unroll
        for (int i = 0; i < 4; i++) {
            int b = b0 + tx + 16 * i;
            float2 o;
            o.x = fmaxf(lo32(acc2[i][0]) + hi32(acc2[i][0]) + pv[i].x, 0.f);
            o.y = fmaxf(lo32(acc2[i][1]) + hi32(acc2[i][1]) + pv[i].y, 0.f);
            __stcg((float2*)&Hout[(size_t)b * NH + n], o);
        }

        __syncthreads();
        __threadfence();
        if (tid == 0) {
            int idx = t * 4 + gid;
            atomicAdd(&ctr[idx], 1);
            while (((volatile int*)ctr)[idx] < GNUM) __nanosleep(32);
        }
        __syncthreads();
        __threadfence();
    }
}

// ---------------- BatchNorm1d (training, biased var) + ReLU ----------------
__global__ void bn_relu(const float* __restrict__ V, const float* __restrict__ gw,
                        const float* __restrict__ bw, float* __restrict__ Y, int cols)
{
    int c = blockIdx.x;
    int t = threadIdx.x;
    float v = V[(size_t)t * cols + c];
    float s = v, ss = v * v;
#pragma unroll
    for (int o = 16; o > 0; o >>= 1) {
        s  += __shfl_down_sync(0xffffffffu, s,  o);
        ss += __shfl_down_sync(0xffffffffu, ss, o);
    }
    __shared__ float rs[4], rq[4];
    if ((t & 31) == 0) { rs[t >> 5] = s; rq[t >> 5] = ss; }
    __syncthreads();
    float S = rs[0] + rs[1] + rs[2] + rs[3];
    float Q = rq[0] + rq[1] + rq[2] + rq[3];
    float mean = S * (1.f / BB);
    float var  = Q * (1.f / BB) - mean * mean;
    float y = (v - mean) * rsqrtf(var + EPSF) * gw[c] + bw[c];
    Y[(size_t)t * cols + c] = fmaxf(y, 0.f);
}

// ---------------- launch ----------------
extern "C" void kernel_launch(void* const* d_in, const int* in_sizes, int n_in,
                              void* d_out, int out_size)
{
    (void)in_sizes; (void)n_in; (void)out_size;
    const float* x     = (const float*)d_in[0];
    const float* h0    = (const float*)d_in[1];
    const float* W_ih0 = (const float*)d_in[2];
    const float* W_hh0 = (const float*)d_in[3];
    const float* b_ih0 = (const float*)d_in[4];
    const float* b_hh0 = (const float*)d_in[5];
    const float* W_ih1 = (const float*)d_in[6];
    const float* W_hh1 = (const float*)d_in[7];
    const float* b_ih1 = (const float*)d_in[8];
    const float* b_hh1 = (const float*)d_in[9];
    const float* bn1_g = (const float*)d_in[10];
    const float* bn1_b = (const float*)d_in[11];
    const float* fc1_W = (const float*)d_in[12];
    const float* fc1_b = (const float*)d_in[13];
    const float* bn2_g = (const float*)d_in[14];
    const float* bn2_b = (const float*)d_in[15];
    const float* fc2_W = (const float*)d_in[16];
    const float* fc2_b = (const float*)d_in[17];
    float* out = (float*)d_out;

    float *P, *H0p, *hi0, *hi1, *h1a, *h1b, *bs0, *bs1, *y1, *z;
    int *c0, *c1;
    cudaGetSymbolAddress((void**)&P,   g_P);
    cudaGetSymbolAddress((void**)&H0p, g_H0buf);
    cudaGetSymbolAddress((void**)&hi0, g_hi0);
    cudaGetSymbolAddress((void**)&hi1, g_hi1);
    cudaGetSymbolAddress((void**)&h1a, g_h1a);
    cudaGetSymbolAddress((void**)&h1b, g_h1b);
    cudaGetSymbolAddress((void**)&bs0, g_bias0);
    cudaGetSymbolAddress((void**)&bs1, g_bias1);
    cudaGetSymbolAddress((void**)&y1,  g_y1);
    cudaGetSymbolAddress((void**)&z,   g_z);
    cudaGetSymbolAddress((void**)&c0,  g_ctr0);
    cudaGetSymbolAddress((void**)&c1,  g_ctr1);

    cudaFuncSetAttribute(rnn_layer<1>, cudaFuncAttributeMaxDynamicSharedMemorySize, RNN_SMEM);
    cudaFuncSetAttribute(rnn_layer<0>, cudaFuncAttributeMaxDynamicSharedMemorySize, RNN_SMEM);

    // 0) biases + initial hidden + barrier counters
    setup_kernel<<<256, 256>>>(h0, b_ih0, b_hh0, b_ih1, b_hh1);

    // 1) P0 = x @ Wih0^T + biases   (34.4 GMAC, tensor cores)
    gemm_tc<1><<<dim3(NH / 128, M_BIG / 128), 256>>>(x, W_ih0, bs0, P, M_BIG, NH, IND);

    // 2) layer-0 recurrence (68.7 GMAC, all timesteps stored)
    rnn_layer<1><<<NCTA, 128, RNN_SMEM>>>(P, hi0, W_hh0, H0p, nullptr, nullptr, c0);

    // 3) P1 = H0 @ Wih1^T + biases  (137.4 GMAC, tensor cores)
    gemm_tc<0><<<dim3(NH / 128, M_BIG / 128), 256>>>(H0p, W_ih1, bs1, P, M_BIG, NH, NH);

    // 4) layer-1 recurrence; final state lands in h1b (t=1023 odd)
    rnn_layer<0><<<NCTA, 128, RNN_SMEM>>>(P, hi1, W_hh1, nullptr, h1a, h1b, c1);

    // 5) head
    bn_relu<<<NH, 128>>>(h1b, bn1_g, bn1_b, y1, NH);
    gemm_bias<0><<<dim3(FC1N / 64, BB / 64), 256>>>(y1, fc1_W, fc1_b, z, BB, FC1N, NH);
    bn_relu<<<FC1N, 128>>>(z, bn2_g, bn2_b, z, FC1N);
    gemm_bias<2><<<dim3(OUTN / 64, BB / 64), 256>>>(z, fc2_W, fc2_b, out, BB, OUTN, FC1N);
}

// round 8
// speedup vs baseline: 1.6172x; 1.4039x over previous
#include <cuda_runtime.h>
#include <math.h>

#define BB    128
#define TT    1024
#define IND   256
#define HH    512
#define NH    1024          // 2*H
#define FC1N  2048
#define OUTN  128
#define EPSF  1e-5f

#define M_BIG (TT * BB)
#define NCTA  128
#define GNUM  16            // CTAs per sync group (bt x direction)

// rnn_mma smem: W hi/lo [32][516] + A hi/lo [32][260]  (floats)
#define WST   516
#define AST   260
#define SM_WH 0
#define SM_WL (32 * WST)
#define SM_AH (2 * 32 * WST)
#define SM_AL (2 * 32 * WST + 32 * AST)
#define RNN_SMEM ((2 * 32 * WST + 2 * 32 * AST) * 4)   // 198,656 bytes

// tf32 split: x ~= hi + lo, both tf32-valued (bit patterns in unsigned)
__device__ __forceinline__ void tf32_split(float x, unsigned &hi, unsigned &lo) {
    unsigned h;
    asm("cvt.rna.tf32.f32 %0, %1;" : "=r"(h) : "f"(x));
    float rem = x - __uint_as_float(h);
    unsigned l;
    asm("cvt.rna.tf32.f32 %0, %1;" : "=r"(l) : "f"(rem));
    hi = h; lo = l;
}

// D += A(16x8,row) * B(8x8,col)  tf32 inputs, fp32 accum  (mapping verified R7)
__device__ __forceinline__ void mma8(float* d, const unsigned* a, const unsigned* b) {
    asm volatile(
        "mma.sync.aligned.m16n8k8.row.col.f32.tf32.tf32.f32 "
        "{%0,%1,%2,%3}, {%4,%5,%6,%7}, {%8,%9}, {%0,%1,%2,%3};"
        : "+f"(d[0]), "+f"(d[1]), "+f"(d[2]), "+f"(d[3])
        : "r"(a[0]), "r"(a[1]), "r"(a[2]), "r"(a[3]), "r"(b[0]), "r"(b[1]));
}

// ---------------- device scratch ----------------
__device__ float g_P[TT * BB * NH];      // 512 MB: P0 then P1
__device__ float g_H0buf[TT * BB * NH];  // 512 MB: layer-0 f32 history
__device__ float g_h0H[BB * NH];         // split init, layer 0
__device__ float g_h0L[BB * NH];
__device__ float g_h1H[BB * NH];         // split init, layer 1
__device__ float g_h1L[BB * NH];
__device__ float g_HhA[BB * NH];         // h hi ping-pong
__device__ float g_HhB[BB * NH];
__device__ float g_HlA[BB * NH];         // h lo ping-pong
__device__ float g_HlB[BB * NH];
__device__ float g_h1a[BB * NH];         // layer-1 f32 ping-pong
__device__ float g_h1b[BB * NH];
__device__ float g_bias0[NH];
__device__ float g_bias1[NH];
__device__ float g_y1[BB * NH];
__device__ float g_z[BB * FC1N];
__device__ int   g_ctr0[TT * 8];
__device__ int   g_ctr1[TT * 8];

// ---------------- setup ----------------
__global__ void setup_kernel(const float* __restrict__ h0,
                             const float* __restrict__ bih0, const float* __restrict__ bhh0,
                             const float* __restrict__ bih1, const float* __restrict__ bhh1)
{
    int i0 = blockIdx.x * blockDim.x + threadIdx.x;
    if (i0 < NH) {
        g_bias0[i0] = bih0[i0] + bhh0[i0];
        g_bias1[i0] = bih1[i0] + bhh1[i0];
    }
    if (i0 < TT * 8) { g_ctr0[i0] = 0; g_ctr1[i0] = 0; }
    int stride = gridDim.x * blockDim.x;
    for (int idx = i0; idx < BB * NH; idx += stride) {
        int b = idx >> 10;
        int n = idx & (NH - 1);
        int d = n >> 9;
        int j = n & (HH - 1);
        float v0 = h0[(size_t)(d * BB + b) * HH + j];
        float v1 = h0[(size_t)((2 + d) * BB + b) * HH + j];
        unsigned hh, ll;
        tf32_split(v0, hh, ll);
        g_h0H[idx] = __uint_as_float(hh); g_h0L[idx] = __uint_as_float(ll);
        tf32_split(v1, hh, ll);
        g_h1H[idx] = __uint_as_float(hh); g_h1L[idx] = __uint_as_float(ll);
    }
}

// ---------------- tensor-core GEMM (tf32x3): C[M,N] = A[M,K] * W[N,K]^T + bias ----------
#define SK 20
template<int AMODE>
__global__ void __launch_bounds__(256) gemm_tc(
    const float* __restrict__ A, const float* __restrict__ W,
    const float* __restrict__ bias, float* __restrict__ C,
    int M, int N, int K)
{
    __shared__ unsigned sAh[128][SK];
    __shared__ unsigned sAl[128][SK];
    __shared__ unsigned sWh[128][SK];
    __shared__ unsigned sWl[128][SK];

    const int m0   = blockIdx.y * 128;
    const int n0   = blockIdx.x * 128;
    const int tid  = threadIdx.x;
    const int lane = tid & 31;
    const int warp = tid >> 5;
    const int wm   = (warp & 1) * 64;
    const int wn   = (warp >> 1) * 32;
    const int r    = lane >> 2;
    const int q    = lane & 3;

    const int srow = tid >> 1;
    const int scg  = (tid & 1) * 8;

    float acc[4][4][4];
#pragma unroll
    for (int i = 0; i < 4; i++)
#pragma unroll
        for (int j = 0; j < 4; j++)
#pragma unroll
            for (int c = 0; c < 4; c++) acc[i][j][c] = 0.f;

    const float* arow;
    {
        int m = m0 + srow;
        if (AMODE == 1) arow = A + ((size_t)((m & (BB - 1)) * TT + (m >> 7))) * K;
        else            arow = A + (size_t)m * K;
    }
    const float* wrow = W + (size_t)(n0 + srow) * K;

    for (int k0 = 0; k0 < K; k0 += 16) {
        float4 av0 = *(const float4*)&arow[k0 + scg];
        float4 av1 = *(const float4*)&arow[k0 + scg + 4];
        float4 wv0 = *(const float4*)&wrow[k0 + scg];
        float4 wv1 = *(const float4*)&wrow[k0 + scg + 4];
        const float* af = (const float*)&av0;
#pragma unroll
        for (int j = 0; j < 4; j++) tf32_split(af[j], sAh[srow][scg + j], sAl[srow][scg + j]);
        af = (const float*)&av1;
#pragma unroll
        for (int j = 0; j < 4; j++) tf32_split(af[j], sAh[srow][scg + 4 + j], sAl[srow][scg + 4 + j]);
        const float* wf = (const float*)&wv0;
#pragma unroll
        for (int j = 0; j < 4; j++) tf32_split(wf[j], sWh[srow][scg + j], sWl[srow][scg + j]);
        wf = (const float*)&wv1;
#pragma unroll
        for (int j = 0; j < 4; j++) tf32_split(wf[j], sWh[srow][scg + 4 + j], sWl[srow][scg + 4 + j]);
        __syncthreads();

#pragma unroll
        for (int kk = 0; kk < 16; kk += 8) {
            unsigned bh[4][2], bl[4][2];
#pragma unroll
            for (int nt = 0; nt < 4; nt++) {
                int nn = wn + nt * 8 + r;
                bh[nt][0] = sWh[nn][kk + q];
                bh[nt][1] = sWh[nn][kk + q + 4];
                bl[nt][0] = sWl[nn][kk + q];
                bl[nt][1] = sWl[nn][kk + q + 4];
            }
#pragma unroll
            for (int mt = 0; mt < 4; mt++) {
                int mm = wm + mt * 16 + r;
                unsigned ah[4], al[4];
                ah[0] = sAh[mm][kk + q];     ah[1] = sAh[mm + 8][kk + q];
                ah[2] = sAh[mm][kk + q + 4]; ah[3] = sAh[mm + 8][kk + q + 4];
                al[0] = sAl[mm][kk + q];     al[1] = sAl[mm + 8][kk + q];
                al[2] = sAl[mm][kk + q + 4]; al[3] = sAl[mm + 8][kk + q + 4];
#pragma unroll
                for (int nt = 0; nt < 4; nt++) {
                    mma8(acc[mt][nt], ah, bh[nt]);
                    mma8(acc[mt][nt], ah, bl[nt]);
                    mma8(acc[mt][nt], al, bh[nt]);
                }
            }
        }
        __syncthreads();
    }

#pragma unroll
    for (int mt = 0; mt < 4; mt++) {
#pragma unroll
        for (int nt = 0; nt < 4; nt++) {
            int n  = n0 + wn + nt * 8 + q * 2;
            int ml = m0 + wm + mt * 16 + r;
            float bx = bias[n], by = bias[n + 1];
            float2 o0 = make_float2(acc[mt][nt][0] + bx, acc[mt][nt][1] + by);
            float2 o1 = make_float2(acc[mt][nt][2] + bx, acc[mt][nt][3] + by);
            *(float2*)&C[(size_t)ml * N + n]       = o0;
            *(float2*)&C[(size_t)(ml + 8) * N + n] = o1;
        }
    }
}

// ---------------- persistent recurrence on tensor cores (tf32x3) ----------------
// 128 CTAs = 4 b-tiles(32 rows) x 32 n-tiles(32 cols). 128 threads (4 warps).
// Warp tile m16 x n16 (2 m16n8 subtiles). W tile split once into smem; A (prev h)
// arrives pre-split (hi/lo global ping-pong written by the epilogue), staged per
// step in two k-halves. Sync groups of 16 CTAs (same b-tile & direction).
template<int LAYER0>
__global__ void __launch_bounds__(128, 1) rnn_mma(
    const float* __restrict__ P, const float* __restrict__ WhhG,
    const float* __restrict__ h0H, const float* __restrict__ h0L,
    float* __restrict__ Hbuf, float* __restrict__ f32A, float* __restrict__ f32B,
    float* __restrict__ HhA, float* __restrict__ HhB,
    float* __restrict__ HlA, float* __restrict__ HlB,
    int* __restrict__ ctr)
{
    extern __shared__ float sm[];
    float* sWh = sm + SM_WH;
    float* sWl = sm + SM_WL;
    float* sAh = sm + SM_AH;
    float* sAl = sm + SM_AL;
    const unsigned* uWh = (const unsigned*)sWh;
    const unsigned* uWl = (const unsigned*)sWl;
    const unsigned* uAh = (const unsigned*)sAh;
    const unsigned* uAl = (const unsigned*)sAl;

    const int tid   = threadIdx.x;
    const int lane  = tid & 31;
    const int warp  = tid >> 5;
    const int r     = lane >> 2;
    const int q     = lane & 3;
    const int mt    = warp & 1;       // m16 tile 0/1
    const int nt    = warp >> 1;      // n16 tile 0/1
    const int bt    = blockIdx.x >> 5;
    const int ntile = blockIdx.x & 31;
    const int b0    = bt * 32;
    const int nBase = ntile * 32;
    const int dir   = ntile >> 4;
    const int gid   = bt * 2 + dir;
    const int dirOff = dir * HH;

    // ---- stage + split this CTA's W tile once (rows nBase..nBase+31, all 512 k) ----
#pragma unroll
    for (int i = 0; i < 32; i++) {
        int idx = tid + i * 128;
        int m = idx >> 7, c4 = idx & 127;
        float4 v = *(const float4*)&WhhG[(size_t)(nBase + m) * HH + c4 * 4];
        const float* vp = (const float*)&v;
#pragma unroll
        for (int j = 0; j < 4; j++) {
            unsigned hh, ll;
            tf32_split(vp[j], hh, ll);
            sWh[m * WST + c4 * 4 + j] = __uint_as_float(hh);
            sWl[m * WST + c4 * 4 + j] = __uint_as_float(ll);
        }
    }
    __syncthreads();

    const int brow0 = b0 + mt * 16 + r;       // output rows brow0, brow0+8
    const int colB  = nBase + nt * 16 + q * 2;

    for (int t = 0; t < TT; t++) {
        const float *HinH, *HinL;
        if (t == 0)           { HinH = h0H; HinL = h0L; }
        else if ((t - 1) & 1) { HinH = HhB; HinL = HlB; }
        else                  { HinH = HhA; HinL = HlA; }
        float* HoutH = (t & 1) ? HhB : HhA;
        float* HoutL = (t & 1) ? HlB : HlA;
        float* Fout  = LAYER0 ? (Hbuf + (size_t)t * BB * NH)
                              : ((t & 1) ? f32B : f32A);

        // prefetch P values for this thread's 8 outputs
        const float* Pt = P + (size_t)t * BB * NH;
        float2 pv[2][2];
#pragma unroll
        for (int sub = 0; sub < 2; sub++) {
            int c = colB + sub * 8;
            pv[sub][0] = *(const float2*)&Pt[(size_t)brow0 * NH + c];
            pv[sub][1] = *(const float2*)&Pt[(size_t)(brow0 + 8) * NH + c];
        }

        float acc[2][4];
#pragma unroll
        for (int s = 0; s < 2; s++)
#pragma unroll
            for (int c = 0; c < 4; c++) acc[s][c] = 0.f;

#pragma unroll
        for (int half = 0; half < 2; half++) {
            // stage A hi/lo for k in [half*256, half*256+256)
#pragma unroll
            for (int i = 0; i < 16; i++) {
                int idx = tid + i * 128;
                int m = idx >> 6, c4 = idx & 63;
                size_t g = (size_t)(b0 + m) * NH + dirOff + half * 256 + c4 * 4;
                float4 vh = __ldcg((const float4*)(HinH + g));
                float4 vl = __ldcg((const float4*)(HinL + g));
                *(float4*)&sAh[m * AST + c4 * 4] = vh;
                *(float4*)&sAl[m * AST + c4 * 4] = vl;
            }
            __syncthreads();

#pragma unroll 4
            for (int kc = 0; kc < 32; kc++) {
                int kk = kc * 8;
                int kw = half * 256 + kk;
                int ar = (mt * 16 + r) * AST + kk + q;
                unsigned ah[4], al[4];
                ah[0] = uAh[ar];            ah[1] = uAh[ar + 8 * AST];
                ah[2] = uAh[ar + 4];        ah[3] = uAh[ar + 8 * AST + 4];
                al[0] = uAl[ar];            al[1] = uAl[ar + 8 * AST];
                al[2] = uAl[ar + 4];        al[3] = uAl[ar + 8 * AST + 4];
#pragma unroll
                for (int sub = 0; sub < 2; sub++) {
                    int br = (nt * 16 + sub * 8 + r) * WST + kw + q;
                    unsigned bh[2] = { uWh[br], uWh[br + 4] };
                    unsigned bl[2] = { uWl[br], uWl[br + 4] };
                    mma8(acc[sub], ah, bh);
                    mma8(acc[sub], ah, bl);
                    mma8(acc[sub], al, bh);
                }
            }
            __syncthreads();
        }

        // ---- epilogue: +P, relu, write f32 + split hi/lo ----
#pragma unroll
        for (int sub = 0; sub < 2; sub++) {
            int c = colB + sub * 8;
            float o00 = fmaxf(acc[sub][0] + pv[sub][0].x, 0.f);
            float o01 = fmaxf(acc[sub][1] + pv[sub][0].y, 0.f);
            float o10 = fmaxf(acc[sub][2] + pv[sub][1].x, 0.f);
            float o11 = fmaxf(acc[sub][3] + pv[sub][1].y, 0.f);
            size_t i0 = (size_t)brow0 * NH + c;
            size_t i1 = (size_t)(brow0 + 8) * NH + c;
            __stcg((float2*)&Fout[i0], make_float2(o00, o01));
            __stcg((float2*)&Fout[i1], make_float2(o10, o11));
            unsigned h00, l00, h01, l01, h10, l10, h11, l11;
            tf32_split(o00, h00, l00); tf32_split(o01, h01, l01);
            tf32_split(o10, h10, l10); tf32_split(o11, h11, l11);
            __stcg((float2*)&HoutH[i0], make_float2(__uint_as_float(h00), __uint_as_float(h01)));
            __stcg((float2*)&HoutH[i1], make_float2(__uint_as_float(h10), __uint_as_float(h11)));
            __stcg((float2*)&HoutL[i0], make_float2(__uint_as_float(l00), __uint_as_float(l01)));
            __stcg((float2*)&HoutL[i1], make_float2(__uint_as_float(l10), __uint_as_float(l11)));
        }

        __syncthreads();
        __threadfence();
        if (tid == 0) {
            int idx = t * 8 + gid;
            atomicAdd(&ctr[idx], 1);
            while (((volatile int*)ctr)[idx] < GNUM) __nanosleep(32);
        }
        __syncthreads();
        __threadfence();
    }
}

// ---------------- small GEMM for head: 64x64 tile ----------------
template<int ACT>
__global__ void __launch_bounds__(256) gemm_bias(
    const float* __restrict__ A, const float* __restrict__ W,
    const float* __restrict__ bias, float* __restrict__ C,
    int M, int N, int K)
{
    __shared__ float sA[16][68];
    __shared__ float sB[16][68];
    const int m0  = blockIdx.y * 64;
    const int n0  = blockIdx.x * 64;
    const int tid = threadIdx.x;
    const int lk  = tid & 15;
    const int lr  = tid >> 4;
    const int tx  = tid & 15;
    const int ty  = tid >> 4;

    float acc[4][4];
#pragma unroll
    for (int i = 0; i < 4; i++)
#pragma unroll
        for (int j = 0; j < 4; j++) acc[i][j] = 0.f;

    for (int k0 = 0; k0 < K; k0 += 16) {
#pragma unroll
        for (int rr = 0; rr < 4; rr++) {
            int m = m0 + lr + rr * 16;
            sA[lk][lr + rr * 16] = A[(size_t)m * K + k0 + lk];
            sB[lk][lr + rr * 16] = W[(size_t)(n0 + lr + rr * 16) * K + k0 + lk];
        }
        __syncthreads();
#pragma unroll
        for (int kk = 0; kk < 16; kk++) {
            float4 a4 = *(const float4*)&sA[kk][tx * 4];
            float4 b4 = *(const float4*)&sB[kk][ty * 4];
            float av[4] = {a4.x, a4.y, a4.z, a4.w};
            float bv[4] = {b4.x, b4.y, b4.z, b4.w};
#pragma unroll
            for (int i = 0; i < 4; i++)
#pragma unroll
                for (int j = 0; j < 4; j++) acc[i][j] += av[i] * bv[j];
        }
        __syncthreads();
    }

#pragma unroll
    for (int i = 0; i < 4; i++) {
        int m = m0 + tx * 4 + i;
        float4 v;
        float* vp = (float*)&v;
#pragma unroll
        for (int j = 0; j < 4; j++) {
            float t = acc[i][j] + bias[n0 + ty * 4 + j];
            if (ACT == 2) t = 1.f / (1.f + expf(-t));
            vp[j] = t;
        }
        *(float4*)&C[(size_t)m * N + n0 + ty * 4] = v;
    }
}

// ---------------- BatchNorm1d (training, biased var) + ReLU ----------------
__global__ void bn_relu(const float* __restrict__ V, const float* __restrict__ gw,
                        const float* __restrict__ bw, float* __restrict__ Y, int cols)
{
    int c = blockIdx.x;
    int t = threadIdx.x;
    float v = V[(size_t)t * cols + c];
    float s = v, ss = v * v;
#pragma unroll
    for (int o = 16; o > 0; o >>= 1) {
        s  += __shfl_down_sync(0xffffffffu, s,  o);
        ss += __shfl_down_sync(0xffffffffu, ss, o);
    }
    __shared__ float rs[4], rq[4];
    if ((t & 31) == 0) { rs[t >> 5] = s; rq[t >> 5] = ss; }
    __syncthreads();
    float S = rs[0] + rs[1] + rs[2] + rs[3];
    float Q = rq[0] + rq[1] + rq[2] + rq[3];
    float mean = S * (1.f / BB);
    float var  = Q * (1.f / BB) - mean * mean;
    float y = (v - mean) * rsqrtf(var + EPSF) * gw[c] + bw[c];
    Y[(size_t)t * cols + c] = fmaxf(y, 0.f);
}

// ---------------- launch ----------------
extern "C" void kernel_launch(void* const* d_in, const int* in_sizes, int n_in,
                              void* d_out, int out_size)
{
    (void)in_sizes; (void)n_in; (void)out_size;
    const float* x     = (const float*)d_in[0];
    const float* h0    = (const float*)d_in[1];
    const float* W_ih0 = (const float*)d_in[2];
    const float* W_hh0 = (const float*)d_in[3];
    const float* b_ih0 = (const float*)d_in[4];
    const float* b_hh0 = (const float*)d_in[5];
    const float* W_ih1 = (const float*)d_in[6];
    const float* W_hh1 = (const float*)d_in[7];
    const float* b_ih1 = (const float*)d_in[8];
    const float* b_hh1 = (const float*)d_in[9];
    const float* bn1_g = (const float*)d_in[10];
    const float* bn1_b = (const float*)d_in[11];
    const float* fc1_W = (const float*)d_in[12];
    const float* fc1_b = (const float*)d_in[13];
    const float* bn2_g = (const float*)d_in[14];
    const float* bn2_b = (const float*)d_in[15];
    const float* fc2_W = (const float*)d_in[16];
    const float* fc2_b = (const float*)d_in[17];
    float* out = (float*)d_out;

    float *P, *H0p, *h0Hp, *h0Lp, *h1Hp, *h1Lp, *HhA, *HhB, *HlA, *HlB;
    float *h1a, *h1b, *bs0, *bs1, *y1, *z;
    int *c0, *c1;
    cudaGetSymbolAddress((void**)&P,    g_P);
    cudaGetSymbolAddress((void**)&H0p,  g_H0buf);
    cudaGetSymbolAddress((void**)&h0Hp, g_h0H);
    cudaGetSymbolAddress((void**)&h0Lp, g_h0L);
    cudaGetSymbolAddress((void**)&h1Hp, g_h1H);
    cudaGetSymbolAddress((void**)&h1Lp, g_h1L);
    cudaGetSymbolAddress((void**)&HhA,  g_HhA);
    cudaGetSymbolAddress((void**)&HhB,  g_HhB);
    cudaGetSymbolAddress((void**)&HlA,  g_HlA);
    cudaGetSymbolAddress((void**)&HlB,  g_HlB);
    cudaGetSymbolAddress((void**)&h1a,  g_h1a);
    cudaGetSymbolAddress((void**)&h1b,  g_h1b);
    cudaGetSymbolAddress((void**)&bs0,  g_bias0);
    cudaGetSymbolAddress((void**)&bs1,  g_bias1);
    cudaGetSymbolAddress((void**)&y1,   g_y1);
    cudaGetSymbolAddress((void**)&z,    g_z);
    cudaGetSymbolAddress((void**)&c0,   g_ctr0);
    cudaGetSymbolAddress((void**)&c1,   g_ctr1);

    cudaFuncSetAttribute(rnn_mma<1>, cudaFuncAttributeMaxDynamicSharedMemorySize, RNN_SMEM);
    cudaFuncSetAttribute(rnn_mma<0>, cudaFuncAttributeMaxDynamicSharedMemorySize, RNN_SMEM);

    // 0) biases + split initial hidden + barrier counters
    setup_kernel<<<256, 256>>>(h0, b_ih0, b_hh0, b_ih1, b_hh1);

    // 1) P0 = x @ Wih0^T + biases   (tensor cores)
    gemm_tc<1><<<dim3(NH / 128, M_BIG / 128), 256>>>(x, W_ih0, bs0, P, M_BIG, NH, IND);

    // 2) layer-0 recurrence (tensor cores, all timesteps stored f32)
    rnn_mma<1><<<NCTA, 128, RNN_SMEM>>>(P, W_hh0, h0Hp, h0Lp, H0p, nullptr, nullptr,
                                        HhA, HhB, HlA, HlB, c0);

    // 3) P1 = H0 @ Wih1^T + biases  (tensor cores)
    gemm_tc<0><<<dim3(NH / 128, M_BIG / 128), 256>>>(H0p, W_ih1, bs1, P, M_BIG, NH, NH);

    // 4) layer-1 recurrence; final f32 state lands in h1b (t=1023 odd)
    rnn_mma<0><<<NCTA, 128, RNN_SMEM>>>(P, W_hh1, h1Hp, h1Lp, nullptr, h1a, h1b,
                                        HhA, HhB, HlA, HlB, c1);

    // 5) head
    bn_relu<<<NH, 128>>>(h1b, bn1_g, bn1_b, y1, NH);
    gemm_bias<0><<<dim3(FC1N / 64, BB / 64), 256>>>(y1, fc1_W, fc1_b, z, BB, FC1N, NH);
    bn_relu<<<FC1N, 128>>>(z, bn2_g, bn2_b, z, FC1N);
    gemm_bias<2><<<dim3(OUTN / 64, BB / 64), 256>>>(z, fc2_W, fc2_b, out, BB, OUTN, FC1N);
}